// round 15
// baseline (speedup 1.0000x reference)
#include <cuda_runtime.h>
#include <cuda_fp16.h>
#include <cstdint>

// ---------------- problem constants ----------------
constexpr int NB = 8, NT = 2048, ND = 1024, NF = 4096, NE = 8, NP = 16;
constexpr int BM = 256, BN = 128, BK = 64;
constexpr int THREADS = 640;          // 16 consumer warps + 4 producer warps
constexpr int NCONS = 512;            // consumer threads

// smem layout (bytes): A row = 64*2+16 = 144B, B row = 128*2+16 = 272B
constexpr int A_STRIDE_B = 144;
constexpr int B_STRIDE_B = 272;
constexpr int A_TILE = BM * A_STRIDE_B;            // 36864
constexpr int B_TILE = BK * B_STRIDE_B;            // 17408
constexpr int BOFF   = A_TILE;
constexpr int BUF    = A_TILE + B_TILE;            // 54272
constexpr int NSTAGE = 4;
constexpr int SMEM_TOTAL = NSTAGE * BUF;           // 217088 (1 CTA/SM)

// ---------------- device scratch (allocation-free) ----------------
__device__ float g_ppart[NB * ND * 16];
__device__ int   g_eidx[NP];
__device__ float g_wgt[NP];
__device__ __half g_x[(size_t)NB*NT*ND];
__device__ __half g_w1[(size_t)NE*ND*NF];
__device__ __half g_w2[(size_t)NE*NF*ND];
__device__ __half g_h[(size_t)NP*NT*NF];

// ---------------- PTX helpers ----------------
__device__ __forceinline__ uint32_t s2u(const void* p) {
    uint32_t a;
    asm("{ .reg .u64 t; cvta.to.shared.u64 t, %1; cvt.u32.u64 %0, t; }" : "=r"(a) : "l"(p));
    return a;
}
__device__ __forceinline__ void cp16(uint32_t dst, const void* src) {
    asm volatile("cp.async.cg.shared.global [%0], [%1], 16;" :: "r"(dst), "l"(src));
}
__device__ __forceinline__ void mbar_init(uint32_t a, uint32_t cnt) {
    asm volatile("mbarrier.init.shared.b64 [%0], %1;" :: "r"(a), "r"(cnt) : "memory");
}
__device__ __forceinline__ void mbar_arrive(uint32_t a) {
    asm volatile("mbarrier.arrive.shared.b64 _, [%0];" :: "r"(a) : "memory");
}
// FIX vs R14: .noinc — each producer thread contributes ONE real arrival when
// its outstanding cp.asyncs complete (default form self-balances and deadlocks).
__device__ __forceinline__ void cp_arrive(uint32_t a) {
    asm volatile("cp.async.mbarrier.arrive.noinc.shared.b64 [%0];" :: "r"(a) : "memory");
}
__device__ __forceinline__ void mbar_wait(uint32_t a, uint32_t ph) {
    asm volatile("{\n\t.reg .pred P;\n\t"
                 "W%=:\n\t"
                 "mbarrier.try_wait.parity.acquire.cta.shared::cta.b64 P, [%0], %1, 0x989680;\n\t"
                 "@!P bra W%=;\n\t}" :: "r"(a), "r"(ph) : "memory");
}
__device__ __forceinline__ void ldm4(uint32_t* r, uint32_t a) {
    asm volatile("ldmatrix.sync.aligned.m8n8.x4.shared.b16 {%0,%1,%2,%3}, [%4];"
        : "=r"(r[0]), "=r"(r[1]), "=r"(r[2]), "=r"(r[3]) : "r"(a));
}
__device__ __forceinline__ void ldm4t(uint32_t* r, uint32_t a) {
    asm volatile("ldmatrix.sync.aligned.m8n8.x4.trans.shared.b16 {%0,%1,%2,%3}, [%4];"
        : "=r"(r[0]), "=r"(r[1]), "=r"(r[2]), "=r"(r[3]) : "r"(a));
}
__device__ __forceinline__ void mma(float* d, const uint32_t* a, uint32_t b0, uint32_t b1) {
    asm volatile("mma.sync.aligned.m16n8k16.row.col.f32.f16.f16.f32 "
        "{%0,%1,%2,%3}, {%4,%5,%6,%7}, {%8,%9}, {%0,%1,%2,%3};"
        : "+f"(d[0]), "+f"(d[1]), "+f"(d[2]), "+f"(d[3])
        : "r"(a[0]), "r"(a[1]), "r"(a[2]), "r"(a[3]), "r"(b0), "r"(b1));
}
__device__ __forceinline__ uint32_t pack_h2(float a, float b) {
    __half2 t = __floats2half2_rn(a, b);
    return *(uint32_t*)&t;
}

// ---------------- prepass kernels ----------------
__global__ void k_pool(const float* __restrict__ x) {
    int b = blockIdx.y, ch = blockIdx.z;
    int d = blockIdx.x * 256 + threadIdx.x;
    const float* xp = x + ((size_t)b * NT + ch * 128) * ND + d;
    float s = 0.f;
#pragma unroll 8
    for (int t = 0; t < 128; ++t) s += xp[(size_t)t * ND];
    g_ppart[(b * ND + d) * 16 + ch] = s;
}

constexpr int N_X4 = NB * NT * ND / 4;
constexpr int N_W4 = NE * ND * NF / 4;
__global__ void k_cvt_all(const float4* __restrict__ x,
                          const float4* __restrict__ W1,
                          const float4* __restrict__ W2) {
    int gid = blockIdx.x * 256 + threadIdx.x;
    const float4* src;  uint32_t* H;  int i;
    if (gid < N_X4) {
        src = x; i = gid;  H = (uint32_t*)g_x;
    } else if (gid < N_X4 + N_W4) {
        src = W1; i = gid - N_X4;  H = (uint32_t*)g_w1;
    } else {
        src = W2; i = gid - N_X4 - N_W4;  H = (uint32_t*)g_w2;
    }
    float4 v = src[i];
    H[2*i]   = pack_h2(v.x, v.y);
    H[2*i+1] = pack_h2(v.z, v.w);
}

__global__ void k_route(const float* __restrict__ Wr) {
    __shared__ float pooled[NB * ND];
    __shared__ float lg[NB][NE];
    int t = threadIdx.x;   // 64 threads
    for (int i = t; i < NB * ND; i += 64) {
        float s = 0.f;
#pragma unroll
        for (int ch = 0; ch < 16; ++ch) s += g_ppart[i * 16 + ch];
        pooled[i] = s * (1.0f / NT);
    }
    __syncthreads();
    if (t < NB * NE) {
        int b = t / NE, e = t % NE;
        float s = 0.f;
        for (int d = 0; d < ND; ++d) s += pooled[b * ND + d] * Wr[d * NE + e];
        lg[b][e] = s;
    }
    __syncthreads();
    if (t < NB) {
        int b = t;
        int i0 = 0; float v0 = lg[b][0];
#pragma unroll
        for (int e = 1; e < NE; ++e) if (lg[b][e] > v0) { v0 = lg[b][e]; i0 = e; }
        int i1 = (i0 == 0) ? 1 : 0; float v1 = lg[b][i1];
#pragma unroll
        for (int e = 0; e < NE; ++e) if (e != i0 && lg[b][e] > v1) { v1 = lg[b][e]; i1 = e; }
        float e1 = expf(v1 - v0);
        float inv = 1.f / (1.f + e1);
        g_eidx[2 * b] = i0;  g_eidx[2 * b + 1] = i1;
        g_wgt[2 * b] = inv;  g_wgt[2 * b + 1] = e1 * inv;
    }
}

// ---------------- GEMM building blocks ----------------
// Producer stage fill: A [256 x 64] (16 cp) + B [64 x 128] (8 cp) per thread.
template<int LDA, int LDB>
__device__ __forceinline__ void fill_stage(uint32_t aDst, const __half* __restrict__ aSrc,
                                           uint32_t bDst, const __half* __restrict__ bSrc)
{
#pragma unroll
    for (int i = 0; i < 16; ++i)
        cp16(aDst + i * 16 * A_STRIDE_B, aSrc + (size_t)i * 16 * LDA);
#pragma unroll
    for (int i = 0; i < 8; ++i)
        cp16(bDst + i * 8 * B_STRIDE_B, bSrc + (size_t)i * 8 * LDB);
}

// Consumer: warp tile 64M x 32N; 4 K16 sub-steps per stage.
__device__ __forceinline__ void compute_stage(uint32_t aB, uint32_t bB, float acc[4][4][4])
{
#pragma unroll
    for (int ks = 0; ks < 4; ++ks) {
        uint32_t bf[2][4];
#pragma unroll
        for (int nt = 0; nt < 2; ++nt)
            ldm4t(bf[nt], bB + ks * 16 * B_STRIDE_B + nt * 32);
#pragma unroll
        for (int mt = 0; mt < 4; ++mt) {
            uint32_t a[4];
            ldm4(a, aB + mt * 16 * A_STRIDE_B + ks * 32);
#pragma unroll
            for (int nt = 0; nt < 2; ++nt)
#pragma unroll
                for (int n8 = 0; n8 < 2; ++n8)
                    mma(acc[mt][nt * 2 + n8], a, bf[nt][2 * n8], bf[nt][2 * n8 + 1]);
        }
    }
}

// ---------------- GEMM1: h[p] = w * gelu(x[b] @ W1[e] + b1[e]) --------------
__global__ __launch_bounds__(THREADS, 1)
void k_mm1(const float* __restrict__ b1) {
    extern __shared__ char sm[];
    __shared__ uint64_t mbar[2 * NSTAGE];          // [0..3]=full, [4..7]=empty
    const uint32_t smb = s2u(sm);
    const uint32_t mbb = s2u(mbar);
    const int tid = threadIdx.x;
    const int p = blockIdx.z, b = p >> 1;
    const int e = g_eidx[p];
    const int m0 = blockIdx.y * BM, n0 = blockIdx.x * BN;
    constexpr int KT = ND / BK;   // 16

    if (tid == 0) {
#pragma unroll
        for (int s = 0; s < NSTAGE; ++s) {
            mbar_init(mbb + s * 8, 128);                 // full: 128 producer threads
            mbar_init(mbb + (NSTAGE + s) * 8, NCONS);    // empty: 512 consumer threads
        }
    }
    __syncthreads();

    if (tid >= NCONS) {
        // ---------------- producer ----------------
        const int pt = tid - NCONS;   // 0..127
        const uint32_t aDst = smb + (pt >> 3) * A_STRIDE_B + (pt & 7) * 16;
        const uint32_t bDst = smb + BOFF + (pt >> 4) * B_STRIDE_B + (pt & 15) * 16;
        const __half* aSrc = g_x  + ((size_t)b * NT + m0 + (pt >> 3)) * ND + (pt & 7) * 8;
        const __half* bSrc = g_w1 + (size_t)e * ND * NF + ((size_t)(pt >> 4)) * NF + n0 + (pt & 15) * 8;
        for (int s = 0; s < KT; ++s) {
            int slot = s & 3;
            if (s >= NSTAGE) mbar_wait(mbb + (NSTAGE + slot) * 8, ((s >> 2) - 1) & 1);
            fill_stage<ND, NF>(aDst + slot * BUF, aSrc, bDst + slot * BUF, bSrc);
            cp_arrive(mbb + slot * 8);
            aSrc += BK;  bSrc += (size_t)BK * NF;
        }
        return;
    }

    // ---------------- consumer ----------------
    const int lane = tid & 31, w = tid >> 5;
    const int warpM = w >> 2, warpN = w & 3;
    const int lr = lane & 15, lc = lane >> 4;
    const float wsc = g_wgt[p];
    const uint32_t aCInv = smb + (warpM * 64 + lr) * A_STRIDE_B + lc * 16;
    const uint32_t bCInv = smb + BOFF + lr * B_STRIDE_B + (warpN * 32 + lc * 8) * 2;

    float acc[4][4][4];
#pragma unroll
    for (int i = 0; i < 4; ++i)
#pragma unroll
        for (int j = 0; j < 4; ++j)
#pragma unroll
            for (int q = 0; q < 4; ++q) acc[i][j][q] = 0.f;

    for (int s = 0; s < KT; ++s) {
        int slot = s & 3;
        mbar_wait(mbb + slot * 8, (s >> 2) & 1);
        compute_stage(aCInv + slot * BUF, bCInv + slot * BUF, acc);
        mbar_arrive(mbb + (NSTAGE + slot) * 8);
    }

    // epilogue: bias + exact erf-gelu + router weight, store h as fp16
    const float* bg = b1 + (size_t)e * NF;
#pragma unroll
    for (int mt = 0; mt < 4; ++mt)
#pragma unroll
        for (int nn = 0; nn < 4; ++nn) {
            int row = m0 + warpM * 64 + mt * 16 + (lane >> 2);
            int col = n0 + warpN * 32 + nn * 8 + (lane & 3) * 2;
            float bv0 = bg[col], bv1 = bg[col + 1];
            float v00 = acc[mt][nn][0] + bv0, v01 = acc[mt][nn][1] + bv1;
            float v10 = acc[mt][nn][2] + bv0, v11 = acc[mt][nn][3] + bv1;
            float g00 = wsc * v00 * normcdff(v00);
            float g01 = wsc * v01 * normcdff(v01);
            float g10 = wsc * v10 * normcdff(v10);
            float g11 = wsc * v11 * normcdff(v11);
            size_t o0 = ((size_t)p * NT + row) * NF + col;
            size_t o1 = ((size_t)p * NT + row + 8) * NF + col;
            *(uint32_t*)&g_h[o0] = pack_h2(g00, g01);
            *(uint32_t*)&g_h[o1] = pack_h2(g10, g11);
        }
}

// ---------------- GEMM2: out[b] = sum_k h[b,k] @ W2[e_k] + weighted bias ----
__global__ __launch_bounds__(THREADS, 1)
void k_mm2(const float* __restrict__ b2, float* __restrict__ out) {
    extern __shared__ char sm[];
    __shared__ uint64_t mbar[2 * NSTAGE];
    const uint32_t smb = s2u(sm);
    const uint32_t mbb = s2u(mbar);
    const int tid = threadIdx.x;
    const int b = blockIdx.z;
    const int e0 = g_eidx[2 * b], e1 = g_eidx[2 * b + 1];
    const int m0 = blockIdx.y * BM, n0 = blockIdx.x * BN;
    constexpr int KSEG = NF / BK;      // 64
    constexpr int KT   = 2 * KSEG;     // 128

    if (tid == 0) {
#pragma unroll
        for (int s = 0; s < NSTAGE; ++s) {
            mbar_init(mbb + s * 8, 128);
            mbar_init(mbb + (NSTAGE + s) * 8, NCONS);
        }
    }
    __syncthreads();

    if (tid >= NCONS) {
        // ---------------- producer ----------------
        const int pt = tid - NCONS;
        const uint32_t aDst = smb + (pt >> 3) * A_STRIDE_B + (pt & 7) * 16;
        const uint32_t bDst = smb + BOFF + (pt >> 4) * B_STRIDE_B + (pt & 15) * 16;
        const size_t aOffT = ((size_t)(pt >> 3)) * NF + (pt & 7) * 8;
        const size_t bOffT = ((size_t)(pt >> 4)) * ND + (pt & 15) * 8;
        const __half* aSrc  = g_h  + ((size_t)(2 * b)     * NT + m0) * NF + aOffT;
        const __half* aSeg1 = g_h  + ((size_t)(2 * b + 1) * NT + m0) * NF + aOffT;
        const __half* bSrc  = g_w2 + (size_t)e0 * NF * ND + n0 + bOffT;
        const __half* bSeg1 = g_w2 + (size_t)e1 * NF * ND + n0 + bOffT;
        for (int s = 0; s < KT; ++s) {
            int slot = s & 3;
            if (s == KSEG) { aSrc = aSeg1; bSrc = bSeg1; }
            if (s >= NSTAGE) mbar_wait(mbb + (NSTAGE + slot) * 8, ((s >> 2) - 1) & 1);
            fill_stage<NF, ND>(aDst + slot * BUF, aSrc, bDst + slot * BUF, bSrc);
            cp_arrive(mbb + slot * 8);
            aSrc += BK;  bSrc += (size_t)BK * ND;
        }
        return;
    }

    // ---------------- consumer ----------------
    const int lane = tid & 31, w = tid >> 5;
    const int warpM = w >> 2, warpN = w & 3;
    const int lr = lane & 15, lc = lane >> 4;
    const float w0 = g_wgt[2 * b], w1 = g_wgt[2 * b + 1];
    const uint32_t aCInv = smb + (warpM * 64 + lr) * A_STRIDE_B + lc * 16;
    const uint32_t bCInv = smb + BOFF + lr * B_STRIDE_B + (warpN * 32 + lc * 8) * 2;

    float acc[4][4][4];
#pragma unroll
    for (int i = 0; i < 4; ++i)
#pragma unroll
        for (int j = 0; j < 4; ++j)
#pragma unroll
            for (int q = 0; q < 4; ++q) acc[i][j][q] = 0.f;

    for (int s = 0; s < KT; ++s) {
        int slot = s & 3;
        mbar_wait(mbb + slot * 8, (s >> 2) & 1);
        compute_stage(aCInv + slot * BUF, bCInv + slot * BUF, acc);
        mbar_arrive(mbb + (NSTAGE + slot) * 8);
    }

    // epilogue: weighted bias, final fp32 output
#pragma unroll
    for (int mt = 0; mt < 4; ++mt)
#pragma unroll
        for (int nn = 0; nn < 4; ++nn) {
            int row = m0 + warpM * 64 + mt * 16 + (lane >> 2);
            int col = n0 + warpN * 32 + nn * 8 + (lane & 3) * 2;
            float bv0 = w0 * b2[e0 * ND + col]     + w1 * b2[e1 * ND + col];
            float bv1 = w0 * b2[e0 * ND + col + 1] + w1 * b2[e1 * ND + col + 1];
            float* o0 = out + ((size_t)b * NT + row) * ND + col;
            float* o1 = out + ((size_t)b * NT + row + 8) * ND + col;
            o0[0] = acc[mt][nn][0] + bv0;  o0[1] = acc[mt][nn][1] + bv1;
            o1[0] = acc[mt][nn][2] + bv0;  o1[1] = acc[mt][nn][3] + bv1;
        }
}

// ---------------- launch (k_mm1 at position 4 for ncu) ----------------------
extern "C" void kernel_launch(void* const* d_in, const int* in_sizes, int n_in,
                              void* d_out, int out_size) {
    const float* x  = (const float*)d_in[0];
    const float* Wr = (const float*)d_in[1];
    const float* W1 = (const float*)d_in[2];
    const float* b1 = (const float*)d_in[3];
    const float* W2 = (const float*)d_in[4];
    const float* b2 = (const float*)d_in[5];
    float* out = (float*)d_out;

    cudaFuncSetAttribute(k_mm1, cudaFuncAttributeMaxDynamicSharedMemorySize, SMEM_TOTAL);
    cudaFuncSetAttribute(k_mm2, cudaFuncAttributeMaxDynamicSharedMemorySize, SMEM_TOTAL);

    k_pool<<<dim3(ND / 256, NB, 16), 256>>>(x);                             // 1
    k_route<<<1, 64>>>(Wr);                                                  // 2
    k_cvt_all<<<(N_X4 + 2 * N_W4 + 255) / 256, 256>>>(
        (const float4*)x, (const float4*)W1, (const float4*)W2);             // 3
    k_mm1<<<dim3(NF/BN, NT/BM, NP), THREADS, SMEM_TOTAL>>>(b1);              // 4 <- ncu
    k_mm2<<<dim3(ND/BN, NT/BM, NB), THREADS, SMEM_TOTAL>>>(b2, out);         // 5
}

// round 16
// speedup vs baseline: 1.0408x; 1.0408x over previous
#include <cuda_runtime.h>
#include <cuda_fp16.h>
#include <cstdint>

// ---------------- problem constants ----------------
constexpr int NB = 8, NT = 2048, ND = 1024, NF = 4096, NE = 8, NP = 16;
constexpr int BM = 128, BN = 128, BK = 64;
constexpr int THREADS = 256;                       // 8 warps, warp tile 64x32

// smem layout (bytes): A row = 64*2+16 = 144B, B row = 128*2+16 = 272B
constexpr int A_STRIDE_B = 144;
constexpr int B_STRIDE_B = 272;
constexpr int A_TILE = BM * A_STRIDE_B;            // 18432
constexpr int B_TILE = BK * B_STRIDE_B;            // 17408
constexpr int BOFF   = A_TILE;                     // 18432
constexpr int BUF    = A_TILE + B_TILE;            // 35840
constexpr int NSTAGE = 3;
constexpr int SMEM_TOTAL = NSTAGE * BUF;           // 107520 (x2 CTAs = 215040 < 228KB)

// ---------------- device scratch (allocation-free) ----------------
__device__ float g_ppart[NB * ND * 16];
__device__ int   g_eidx[NP];
__device__ float g_wgt[NP];
__device__ unsigned g_used;                        // bitmask of selected experts
__device__ __half g_x[(size_t)NB*NT*ND];
__device__ __half g_w1[(size_t)NE*ND*NF];
__device__ __half g_w2[(size_t)NE*NF*ND];
__device__ __half g_h[(size_t)NP*NT*NF];

// ---------------- PTX helpers (arch-neutral, sm_80-era) ----------------
__device__ __forceinline__ uint32_t s2u(const void* p) {
    uint32_t a;
    asm("{ .reg .u64 t; cvta.to.shared.u64 t, %1; cvt.u32.u64 %0, t; }" : "=r"(a) : "l"(p));
    return a;
}
__device__ __forceinline__ void cp16(uint32_t dst, const void* src) {
    asm volatile("cp.async.cg.shared.global [%0], [%1], 16;" :: "r"(dst), "l"(src));
}
#define CP_COMMIT() asm volatile("cp.async.commit_group;" ::: "memory")
#define CP_WAIT(n)  asm volatile("cp.async.wait_group %0;" :: "n"(n) : "memory")

__device__ __forceinline__ void ldm4(uint32_t* r, uint32_t a) {
    asm volatile("ldmatrix.sync.aligned.m8n8.x4.shared.b16 {%0,%1,%2,%3}, [%4];"
        : "=r"(r[0]), "=r"(r[1]), "=r"(r[2]), "=r"(r[3]) : "r"(a));
}
__device__ __forceinline__ void ldm4t(uint32_t* r, uint32_t a) {
    asm volatile("ldmatrix.sync.aligned.m8n8.x4.trans.shared.b16 {%0,%1,%2,%3}, [%4];"
        : "=r"(r[0]), "=r"(r[1]), "=r"(r[2]), "=r"(r[3]) : "r"(a));
}
__device__ __forceinline__ void mma(float* d, const uint32_t* a, uint32_t b0, uint32_t b1) {
    asm volatile("mma.sync.aligned.m16n8k16.row.col.f32.f16.f16.f32 "
        "{%0,%1,%2,%3}, {%4,%5,%6,%7}, {%8,%9}, {%0,%1,%2,%3};"
        : "+f"(d[0]), "+f"(d[1]), "+f"(d[2]), "+f"(d[3])
        : "r"(a[0]), "r"(a[1]), "r"(a[2]), "r"(a[3]), "r"(b0), "r"(b1));
}
__device__ __forceinline__ uint32_t pack_h2(float a, float b) {
    __half2 t = __floats2half2_rn(a, b);
    return *(uint32_t*)&t;
}

// ---------------- prepass kernels ----------------
__global__ void k_pool(const float* __restrict__ x) {
    int b = blockIdx.y, ch = blockIdx.z;
    int d = blockIdx.x * 256 + threadIdx.x;
    const float* xp = x + ((size_t)b * NT + ch * 128) * ND + d;
    float s = 0.f;
#pragma unroll 8
    for (int t = 0; t < 128; ++t) s += xp[(size_t)t * ND];
    g_ppart[(b * ND + d) * 16 + ch] = s;
}

__global__ void k_route(const float* __restrict__ Wr) {
    __shared__ float pooled[NB * ND];
    __shared__ float lg[NB][NE];
    int t = threadIdx.x;   // 64 threads
    for (int i = t; i < NB * ND; i += 64) {
        float s = 0.f;
#pragma unroll
        for (int ch = 0; ch < 16; ++ch) s += g_ppart[i * 16 + ch];
        pooled[i] = s * (1.0f / NT);
    }
    __syncthreads();
    if (t < NB * NE) {
        int b = t / NE, e = t % NE;
        float s = 0.f;
        for (int d = 0; d < ND; ++d) s += pooled[b * ND + d] * Wr[d * NE + e];
        lg[b][e] = s;
    }
    if (t == 0) g_used = 0u;
    __syncthreads();
    if (t < NB) {
        int b = t;
        int i0 = 0; float v0 = lg[b][0];
#pragma unroll
        for (int e = 1; e < NE; ++e) if (lg[b][e] > v0) { v0 = lg[b][e]; i0 = e; }
        int i1 = (i0 == 0) ? 1 : 0; float v1 = lg[b][i1];
#pragma unroll
        for (int e = 0; e < NE; ++e) if (e != i0 && lg[b][e] > v1) { v1 = lg[b][e]; i1 = e; }
        float e1 = expf(v1 - v0);
        float inv = 1.f / (1.f + e1);
        g_eidx[2 * b] = i0;  g_eidx[2 * b + 1] = i1;
        g_wgt[2 * b] = inv;  g_wgt[2 * b + 1] = e1 * inv;
        atomicOr(&g_used, (1u << i0) | (1u << i1));
    }
}

constexpr int N_X4 = NB * NT * ND / 4;
constexpr int N_W4 = NE * ND * NF / 4;
constexpr int W_PER_E4 = ND * NF / 4;       // float4s per expert matrix
__global__ void k_cvt_all(const float4* __restrict__ x,
                          const float4* __restrict__ W1,
                          const float4* __restrict__ W2) {
    int gid = blockIdx.x * 256 + threadIdx.x;
    const float4* src;  uint32_t* H;  int i;
    if (gid < N_X4) {
        src = x; i = gid;  H = (uint32_t*)g_x;
    } else if (gid < N_X4 + N_W4) {
        i = gid - N_X4;
        if (!((g_used >> (i / W_PER_E4)) & 1u)) return;   // skip unused expert
        src = W1;  H = (uint32_t*)g_w1;
    } else {
        i = gid - N_X4 - N_W4;
        if (!((g_used >> (i / W_PER_E4)) & 1u)) return;
        src = W2;  H = (uint32_t*)g_w2;
    }
    float4 v = src[i];
    H[2*i]   = pack_h2(v.x, v.y);
    H[2*i+1] = pack_h2(v.z, v.w);
}

// ---------------- GEMM mainloop pieces (all-constant offsets) ----------------
template<int LDA, int LDB>
__device__ __forceinline__ void load_stage(uint32_t aDst, const __half* __restrict__ aSrc,
                                           uint32_t bDst, const __half* __restrict__ bSrc)
{
#pragma unroll
    for (int i = 0; i < 4; ++i) {
        cp16(aDst + i * 32 * A_STRIDE_B, aSrc + (size_t)i * 32 * LDA);
        cp16(bDst + i * 16 * B_STRIDE_B, bSrc + (size_t)i * 16 * LDB);
    }
}

// Warp tile 64M x 32N; 4 K16 sub-steps; A-fragment double-buffered so each
// ldmatrix lands ~16 mma ahead of its consumer (hides LDS latency).
__device__ __forceinline__ void compute_stage(uint32_t aB, uint32_t bB, float acc[4][4][4])
{
    uint32_t af[2][4];
    ldm4(af[0], aB);                                  // A(ks=0, mt=0)
#pragma unroll
    for (int ks = 0; ks < 4; ++ks) {
        uint32_t bf[2][4];
#pragma unroll
        for (int nt = 0; nt < 2; ++nt)
            ldm4t(bf[nt], bB + ks * 16 * B_STRIDE_B + nt * 32);
#pragma unroll
        for (int mt = 0; mt < 4; ++mt) {
            // prefetch next A fragment before consuming current one
            if (mt < 3)
                ldm4(af[(mt + 1) & 1], aB + (mt + 1) * 16 * A_STRIDE_B + ks * 32);
            else if (ks < 3)
                ldm4(af[0], aB + (ks + 1) * 32);      // A(ks+1, mt=0)
            const uint32_t* a = af[mt & 1];
#pragma unroll
            for (int nt = 0; nt < 2; ++nt)
#pragma unroll
                for (int n8 = 0; n8 < 2; ++n8)
                    mma(acc[mt][nt * 2 + n8], a, bf[nt][2 * n8], bf[nt][2 * n8 + 1]);
        }
    }
}

// ---------------- GEMM1: h[p] = w * gelu(x[b] @ W1[e] + b1[e]) --------------
__global__ __launch_bounds__(THREADS, 2)
void k_mm1(const float* __restrict__ b1) {
    extern __shared__ char sm[];
    const uint32_t smb = s2u(sm);
    const int tid = threadIdx.x, lane = tid & 31, w = tid >> 5;
    const int warpM = w >> 2, warpN = w & 3;
    const int p = blockIdx.z, b = p >> 1;
    const int e = g_eidx[p];
    const float wsc = g_wgt[p];
    const int m0 = blockIdx.y * BM, n0 = blockIdx.x * BN;
    const int lr = lane & 15, lc = lane >> 4;

    const uint32_t aDstInv = smb + (tid >> 3) * A_STRIDE_B + (tid & 7) * 16;
    const uint32_t bDstInv = smb + BOFF + (tid >> 4) * B_STRIDE_B + (tid & 15) * 16;
    const __half* aSrc = g_x  + ((size_t)b * NT + m0 + (tid >> 3)) * ND + (tid & 7) * 8;
    const __half* bSrc = g_w1 + (size_t)e * ND * NF + ((size_t)(tid >> 4)) * NF + n0 + (tid & 15) * 8;
    const uint32_t aCInv = smb + (warpM * 64 + lr) * A_STRIDE_B + lc * 16;
    const uint32_t bCInv = smb + BOFF + lr * B_STRIDE_B + (warpN * 32 + lc * 8) * 2;

    float acc[4][4][4];
#pragma unroll
    for (int i = 0; i < 4; ++i)
#pragma unroll
        for (int j = 0; j < 4; ++j)
#pragma unroll
            for (int q = 0; q < 4; ++q) acc[i][j][q] = 0.f;

    constexpr int KT = ND / BK;   // 16
    load_stage<ND, NF>(aDstInv, aSrc, bDstInv, bSrc);  CP_COMMIT();
    aSrc += BK;  bSrc += (size_t)BK * NF;
    load_stage<ND, NF>(aDstInv + BUF, aSrc, bDstInv + BUF, bSrc);  CP_COMMIT();
    aSrc += BK;  bSrc += (size_t)BK * NF;

    uint32_t bufOff = 0, nbufOff = 2 * BUF;
    for (int s = 0; s < KT; ++s) {
        if (s + 1 < KT) CP_WAIT(1); else CP_WAIT(0);
        __syncthreads();
        if (s + 2 < KT) {
            load_stage<ND, NF>(aDstInv + nbufOff, aSrc, bDstInv + nbufOff, bSrc);
            CP_COMMIT();
            aSrc += BK;  bSrc += (size_t)BK * NF;
        }
        compute_stage(aCInv + bufOff, bCInv + bufOff, acc);
        bufOff += BUF;  if (bufOff == NSTAGE * BUF) bufOff = 0;
        nbufOff += BUF; if (nbufOff == NSTAGE * BUF) nbufOff = 0;
    }

    // epilogue: bias + exact erf-gelu + router weight, store h as fp16
    const float* bg = b1 + (size_t)e * NF;
#pragma unroll
    for (int mt = 0; mt < 4; ++mt)
#pragma unroll
        for (int nn = 0; nn < 4; ++nn) {
            int row = m0 + warpM * 64 + mt * 16 + (lane >> 2);
            int col = n0 + warpN * 32 + nn * 8 + (lane & 3) * 2;
            float bv0 = bg[col], bv1 = bg[col + 1];
            float v00 = acc[mt][nn][0] + bv0, v01 = acc[mt][nn][1] + bv1;
            float v10 = acc[mt][nn][2] + bv0, v11 = acc[mt][nn][3] + bv1;
            float g00 = wsc * v00 * normcdff(v00);
            float g01 = wsc * v01 * normcdff(v01);
            float g10 = wsc * v10 * normcdff(v10);
            float g11 = wsc * v11 * normcdff(v11);
            size_t o0 = ((size_t)p * NT + row) * NF + col;
            size_t o1 = ((size_t)p * NT + row + 8) * NF + col;
            *(uint32_t*)&g_h[o0] = pack_h2(g00, g01);
            *(uint32_t*)&g_h[o1] = pack_h2(g10, g11);
        }
}

// ---------------- GEMM2: out[b] = sum_k h[b,k] @ W2[e_k] + weighted bias ----
__global__ __launch_bounds__(THREADS, 2)
void k_mm2(const float* __restrict__ b2, float* __restrict__ out) {
    extern __shared__ char sm[];
    const uint32_t smb = s2u(sm);
    const int tid = threadIdx.x, lane = tid & 31, w = tid >> 5;
    const int warpM = w >> 2, warpN = w & 3;
    const int b = blockIdx.z;
    const int e0 = g_eidx[2 * b], e1 = g_eidx[2 * b + 1];
    const float w0 = g_wgt[2 * b], w1 = g_wgt[2 * b + 1];
    const int m0 = blockIdx.y * BM, n0 = blockIdx.x * BN;
    const int lr = lane & 15, lc = lane >> 4;

    const uint32_t aDstInv = smb + (tid >> 3) * A_STRIDE_B + (tid & 7) * 16;
    const uint32_t bDstInv = smb + BOFF + (tid >> 4) * B_STRIDE_B + (tid & 15) * 16;
    const size_t aOffT = ((size_t)(tid >> 3)) * NF + (tid & 7) * 8;
    const size_t bOffT = ((size_t)(tid >> 4)) * ND + (tid & 15) * 8;
    const __half* aSrc  = g_h  + ((size_t)(2 * b)     * NT + m0) * NF + aOffT;
    const __half* aSeg1 = g_h  + ((size_t)(2 * b + 1) * NT + m0) * NF + aOffT;
    const __half* bSrc  = g_w2 + (size_t)e0 * NF * ND + n0 + bOffT;
    const __half* bSeg1 = g_w2 + (size_t)e1 * NF * ND + n0 + bOffT;
    const uint32_t aCInv = smb + (warpM * 64 + lr) * A_STRIDE_B + lc * 16;
    const uint32_t bCInv = smb + BOFF + lr * B_STRIDE_B + (warpN * 32 + lc * 8) * 2;

    float acc[4][4][4];
#pragma unroll
    for (int i = 0; i < 4; ++i)
#pragma unroll
        for (int j = 0; j < 4; ++j)
#pragma unroll
            for (int q = 0; q < 4; ++q) acc[i][j][q] = 0.f;

    constexpr int KSEG = NF / BK;      // 64 stages per expert
    constexpr int KT   = 2 * KSEG;     // 128

    load_stage<NF, ND>(aDstInv, aSrc, bDstInv, bSrc);  CP_COMMIT();
    aSrc += BK;  bSrc += (size_t)BK * ND;
    load_stage<NF, ND>(aDstInv + BUF, aSrc, bDstInv + BUF, bSrc);  CP_COMMIT();
    aSrc += BK;  bSrc += (size_t)BK * ND;

    uint32_t bufOff = 0, nbufOff = 2 * BUF;
    for (int s = 0; s < KT; ++s) {
        if (s + 1 < KT) CP_WAIT(1); else CP_WAIT(0);
        __syncthreads();
        if (s + 2 < KT) {
            if (s + 2 == KSEG) { aSrc = aSeg1; bSrc = bSeg1; }
            load_stage<NF, ND>(aDstInv + nbufOff, aSrc, bDstInv + nbufOff, bSrc);
            CP_COMMIT();
            aSrc += BK;  bSrc += (size_t)BK * ND;
        }
        compute_stage(aCInv + bufOff, bCInv + bufOff, acc);
        bufOff += BUF;  if (bufOff == NSTAGE * BUF) bufOff = 0;
        nbufOff += BUF; if (nbufOff == NSTAGE * BUF) nbufOff = 0;
    }

    // epilogue: weighted bias, final fp32 output
#pragma unroll
    for (int mt = 0; mt < 4; ++mt)
#pragma unroll
        for (int nn = 0; nn < 4; ++nn) {
            int row = m0 + warpM * 64 + mt * 16 + (lane >> 2);
            int col = n0 + warpN * 32 + nn * 8 + (lane & 3) * 2;
            float bv0 = w0 * b2[e0 * ND + col]     + w1 * b2[e1 * ND + col];
            float bv1 = w0 * b2[e0 * ND + col + 1] + w1 * b2[e1 * ND + col + 1];
            float* o0 = out + ((size_t)b * NT + row) * ND + col;
            float* o1 = out + ((size_t)b * NT + row + 8) * ND + col;
            o0[0] = acc[mt][nn][0] + bv0;  o0[1] = acc[mt][nn][1] + bv1;
            o1[0] = acc[mt][nn][2] + bv0;  o1[1] = acc[mt][nn][3] + bv1;
        }
}

// ---------------- launch (k_mm1 at position 4 for ncu) ----------------------
extern "C" void kernel_launch(void* const* d_in, const int* in_sizes, int n_in,
                              void* d_out, int out_size) {
    const float* x  = (const float*)d_in[0];
    const float* Wr = (const float*)d_in[1];
    const float* W1 = (const float*)d_in[2];
    const float* b1 = (const float*)d_in[3];
    const float* W2 = (const float*)d_in[4];
    const float* b2 = (const float*)d_in[5];
    float* out = (float*)d_out;

    cudaFuncSetAttribute(k_mm1, cudaFuncAttributeMaxDynamicSharedMemorySize, SMEM_TOTAL);
    cudaFuncSetAttribute(k_mm2, cudaFuncAttributeMaxDynamicSharedMemorySize, SMEM_TOTAL);

    k_pool<<<dim3(ND / 256, NB, 16), 256>>>(x);                             // 1
    k_route<<<1, 64>>>(Wr);                                                  // 2 (sets g_used)
    k_cvt_all<<<(N_X4 + 2 * N_W4 + 255) / 256, 256>>>(
        (const float4*)x, (const float4*)W1, (const float4*)W2);             // 3 (skips unused)
    k_mm1<<<dim3(NF/BN, NT/BM, NP), THREADS, SMEM_TOTAL>>>(b1);              // 4 <- ncu
    k_mm2<<<dim3(ND/BN, NT/BM, NB), THREADS, SMEM_TOTAL>>>(b2, out);         // 5
}